// round 11
// baseline (speedup 1.0000x reference)
#include <cuda_runtime.h>
#include <cuda_fp16.h>
#include <cstdint>
#include <math.h>

// Problem constants
#define BATCH   512
#define NTOK    64
#define C_DIM   768
#define K2DIM   2304          // 3*C
#define TOKENS  (BATCH * NTOK)   // 32768

// ---------------- device scratch (no allocation allowed) ----------------
__device__ __half g_xfuse[(size_t)TOKENS * K2DIM];   // [token][3C], fp16
__device__ __half g_y[(size_t)TOKENS * C_DIM];       // stage-2 output, fp16
__device__ __half g_fc2p[C_DIM * K2DIM];             // fc2 * ln2_w, fp16
__device__ __half g_projp[C_DIM * C_DIM];            // proj_w, fp16
__device__ float  g_colsum[C_DIM];                   // sum_k ln2_w[k]*fc2[o,k]
__device__ float  g_bsum[C_DIM];                     // sum_k ln2_b[k]*fc2[o,k]

// ---------------- helpers ----------------
__device__ __forceinline__ float tanh_fast(float x) {
    float y;
    asm("tanh.approx.f32 %0, %1;" : "=f"(y) : "f"(x));
    return y;
}
__device__ __forceinline__ float gelu_t(float x) {
    float u = 0.7978845608028654f * (x + 0.044715f * x * x * x);
    return 0.5f * x * (1.0f + tanh_fast(u));
}

// ---------------- K0: fused weight prep ----------------
__global__ __launch_bounds__(256) void prep_all(
        const float* __restrict__ fc2, const float* __restrict__ w,
        const float* __restrict__ b, const float* __restrict__ proj) {
    int o = blockIdx.x;
    int tid = threadIdx.x;
    float cs = 0.f, bs = 0.f;
    for (int k = tid; k < K2DIM; k += 256) {
        float f = fc2[o * K2DIM + k];
        float wk = w[k];
        g_fc2p[o * K2DIM + k] = __float2half_rn(f * wk);
        cs += f * wk;
        bs += f * b[k];
    }
    for (int k = tid; k < C_DIM; k += 256)
        g_projp[o * C_DIM + k] = __float2half_rn(proj[o * C_DIM + k]);

    __shared__ float scs[8], sbs[8];
    #pragma unroll
    for (int off = 16; off; off >>= 1) {
        cs += __shfl_down_sync(0xffffffffu, cs, off);
        bs += __shfl_down_sync(0xffffffffu, bs, off);
    }
    int wid = tid >> 5, lane = tid & 31;
    if (lane == 0) { scs[wid] = cs; sbs[wid] = bs; }
    __syncthreads();
    if (tid == 0) {
        float c2 = 0.f, b2 = 0.f;
        for (int i = 0; i < 8; i++) { c2 += scs[i]; b2 += sbs[i]; }
        g_colsum[o] = c2; g_bsum[o] = b2;
    }
}

// ---------------- K1: per-(b,c) 8x8 mixing (streaming, low-reg) ----------------
__global__ __launch_bounds__(256, 2) void stage1(
        const float* __restrict__ x,
        const float* __restrict__ ln1w, const float* __restrict__ ln1b,
        const float* __restrict__ fc1w) {
    __shared__ float s_fc1[64], s_w[8], s_b[8];
    int tid = threadIdx.x;
    if (tid < 64) s_fc1[tid] = fc1w[tid];
    if (tid < 8) { s_w[tid] = ln1w[tid]; s_b[tid] = ln1b[tid]; }
    __syncthreads();

    int b = blockIdx.x;
    int c = blockIdx.y * 256 + tid;          // grid.y = 3 -> c in [0,768)
    const float* xb = x + (size_t)b * NTOK * C_DIM;
    __half* rowbase = g_xfuse + (size_t)b * NTOK * K2DIM;

    float M[64];
    #pragma unroll
    for (int n = 0; n < 64; n++) M[n] = xb[n * C_DIM + c];

    // x5 part
    #pragma unroll
    for (int n = 0; n < 64; n++)
        rowbase[(size_t)n * K2DIM + c] = __float2half_rn(M[n]);

    // column LN -> A column j -> xh column j (streamed)
    #pragma unroll
    for (int j = 0; j < 8; j++) {
        float m = 0.f;
        #pragma unroll
        for (int t = 0; t < 8; t++) m += M[t * 8 + j];
        m *= 0.125f;
        float v = 0.f;
        #pragma unroll
        for (int t = 0; t < 8; t++) { float d = M[t * 8 + j] - m; v += d * d; }
        float rs = rsqrtf(v * 0.125f + 1e-5f);
        float ln[8];
        #pragma unroll
        for (int t = 0; t < 8; t++)
            ln[t] = (M[t * 8 + j] - m) * rs * s_w[t] + s_b[t];
        float acol[8];
        #pragma unroll
        for (int io = 0; io < 8; io++) {
            float a = 0.f;
            #pragma unroll
            for (int t = 0; t < 8; t++) a += s_fc1[io * 8 + t] * ln[t];
            acol[io] = gelu_t(a);
        }
        #pragma unroll
        for (int i = 0; i < 8; i++) {
            float xh = 0.f;
            #pragma unroll
            for (int t = 0; t < 8; t++) xh += M[i * 8 + t] * acol[t];
            rowbase[(size_t)(i * 8 + j) * K2DIM + C_DIM + c] = __float2half_rn(xh);
        }
    }
    // row LN -> W row i -> xw row i (streamed)
    #pragma unroll
    for (int i = 0; i < 8; i++) {
        float m = 0.f;
        #pragma unroll
        for (int t = 0; t < 8; t++) m += M[i * 8 + t];
        m *= 0.125f;
        float v = 0.f;
        #pragma unroll
        for (int t = 0; t < 8; t++) { float d = M[i * 8 + t] - m; v += d * d; }
        float rs = rsqrtf(v * 0.125f + 1e-5f);
        float ln[8];
        #pragma unroll
        for (int t = 0; t < 8; t++)
            ln[t] = (M[i * 8 + t] - m) * rs * s_w[t] + s_b[t];
        float wrow[8];
        #pragma unroll
        for (int jo = 0; jo < 8; jo++) {
            float a = 0.f;
            #pragma unroll
            for (int t = 0; t < 8; t++) a += ln[t] * s_fc1[jo * 8 + t];
            wrow[jo] = gelu_t(a);
        }
        #pragma unroll
        for (int j = 0; j < 8; j++) {
            float xw = 0.f;
            #pragma unroll
            for (int t = 0; t < 8; t++) xw += wrow[t] * M[t * 8 + j];
            rowbase[(size_t)(i * 8 + j) * K2DIM + 2 * C_DIM + c] = __float2half_rn(xw);
        }
    }
}

// ---------------- K2: FP16 GEMM, f32 acc, ring-5, 2 stages/barrier ------------
// (unchanged R10 best config: BM=BN=128, warp tile 64x32, 2 CTAs/SM)
#define BM 128
#define BN 128
#define BK 32
#define LDH 40
#define NSLOT 5
#define TILE_H (BM * LDH)
#define STAGE_BYTES (2 * TILE_H * 2)
#define SMEM_BYTES (NSLOT * STAGE_BYTES)      // 102400 B
#define GTHREADS 256

__device__ __forceinline__ void cp16(uint32_t smem, const void* g) {
    asm volatile("cp.async.cg.shared.global [%0], [%1], 16;\n" :: "r"(smem), "l"(g));
}

__global__ __launch_bounds__(GTHREADS, 2) void gemm_k2(
        const __half* __restrict__ Ag, const __half* __restrict__ Bg,
        __half* __restrict__ CoutH) {
    extern __shared__ __half smh[];
    __shared__ float s_m[BM], s_r[BM], s_c0[BN], s_c1[BN];
    const int KDIM = K2DIM;

    int tid = threadIdx.x;
    int rowA0 = blockIdx.y * BM;
    int colB0 = blockIdx.x * BN;
    const __half* Abase = Ag + (size_t)rowA0 * KDIM;
    const __half* Bbase = Bg + (size_t)colB0 * KDIM;

    uint32_t smem_u = (uint32_t)__cvta_generic_to_shared(smh);

    int lr = tid >> 1;
    int lc = (tid & 1) * 16;
    uint32_t sOffA = (uint32_t)((lr * LDH + lc) * 2);
    uint32_t sOffB = sOffA + TILE_H * 2;

    auto load_body = [&](int slot, int kt) {
        uint32_t base = smem_u + (uint32_t)slot * STAGE_BYTES;
        const __half* a0 = Abase + (size_t)lr * KDIM + kt * BK + lc;
        cp16(base + sOffA,      a0);
        cp16(base + sOffA + 16, a0 + 8);
        const __half* b0 = Bbase + (size_t)lr * KDIM + kt * BK + lc;
        cp16(base + sOffB,      b0);
        cp16(base + sOffB + 16, b0 + 8);
    };

    const int KT = KDIM / BK;        // 72
    #pragma unroll
    for (int p = 0; p < 3; p++) {
        load_body(p, p);
        asm volatile("cp.async.commit_group;\n");
    }

    int wid = tid >> 5, lane = tid & 31;
    int wm = (wid & 1) * 64;
    int wn = (wid >> 1) * 32;

    uint32_t offA[4];
    #pragma unroll
    for (int mm = 0; mm < 4; mm++) {
        int row = wm + mm * 16 + (lane & 15);
        int kb  = lane >> 4;
        offA[mm] = (uint32_t)((row * LDH + kb * 8) * 2);
    }
    uint32_t offB[2];
    #pragma unroll
    for (int nn2 = 0; nn2 < 2; nn2++) {
        int n  = wn + nn2 * 16 + (lane & 7) + ((lane >> 4) ? 8 : 0);
        int kb = (lane >> 3) & 1;
        offB[nn2] = (uint32_t)((n * LDH + kb * 8) * 2 + TILE_H * 2);
    }

    float acc[4][4][4];
    #pragma unroll
    for (int a = 0; a < 4; a++)
        #pragma unroll
        for (int b2 = 0; b2 < 4; b2++)
            #pragma unroll
            for (int c2 = 0; c2 < 4; c2++) acc[a][b2][c2] = 0.f;

    float rsum0 = 0.f, rsq0 = 0.f, rsum1 = 0.f, rsq1 = 0.f;
    int srow = tid & 127, skh = (tid >> 7) * 16;
    uint32_t statOff = (uint32_t)((srow * LDH + skh) * 2);

    auto compute_stage = [&](int slot) {
        uint32_t stage = smem_u + (uint32_t)slot * STAGE_BYTES;

        {   // per-token LN stats (16 halves per thread per stage), 2 partial chains
            uint4 q0, q1;
            asm volatile("ld.shared.v4.u32 {%0,%1,%2,%3}, [%4];"
                         : "=r"(q0.x), "=r"(q0.y), "=r"(q0.z), "=r"(q0.w)
                         : "r"(stage + statOff));
            asm volatile("ld.shared.v4.u32 {%0,%1,%2,%3}, [%4];"
                         : "=r"(q1.x), "=r"(q1.y), "=r"(q1.z), "=r"(q1.w)
                         : "r"(stage + statOff + 16));
            const uint32_t wv0[4] = {q0.x, q0.y, q0.z, q0.w};
            const uint32_t wv1[4] = {q1.x, q1.y, q1.z, q1.w};
            #pragma unroll
            for (int wq = 0; wq < 4; wq++) {
                __half2 h0 = *reinterpret_cast<const __half2*>(&wv0[wq]);
                float2 f0 = __half22float2(h0);
                rsum0 += f0.x + f0.y;
                rsq0  += f0.x * f0.x + f0.y * f0.y;
                __half2 h1 = *reinterpret_cast<const __half2*>(&wv1[wq]);
                float2 f1 = __half22float2(h1);
                rsum1 += f1.x + f1.y;
                rsq1  += f1.x * f1.x + f1.y * f1.y;
            }
        }

        #pragma unroll
        for (int kk = 0; kk < BK; kk += 16) {
            uint32_t af[4][4], bf[2][4];
            #pragma unroll
            for (int mm = 0; mm < 4; mm++)
                asm volatile(
                    "ldmatrix.sync.aligned.m8n8.x4.shared.b16 {%0,%1,%2,%3}, [%4];\n"
                    : "=r"(af[mm][0]), "=r"(af[mm][1]), "=r"(af[mm][2]), "=r"(af[mm][3])
                    : "r"(stage + offA[mm] + kk * 2));
            #pragma unroll
            for (int nn2 = 0; nn2 < 2; nn2++)
                asm volatile(
                    "ldmatrix.sync.aligned.m8n8.x4.shared.b16 {%0,%1,%2,%3}, [%4];\n"
                    : "=r"(bf[nn2][0]), "=r"(bf[nn2][1]), "=r"(bf[nn2][2]), "=r"(bf[nn2][3])
                    : "r"(stage + offB[nn2] + kk * 2));

            #pragma unroll
            for (int mm = 0; mm < 4; mm++)
                #pragma unroll
                for (int nn = 0; nn < 4; nn++) {
                    const uint32_t b0 = bf[nn >> 1][(nn & 1) * 2 + 0];
                    const uint32_t b1 = bf[nn >> 1][(nn & 1) * 2 + 1];
                    asm volatile(
                        "mma.sync.aligned.m16n8k16.row.col.f32.f16.f16.f32 "
                        "{%0,%1,%2,%3}, {%4,%5,%6,%7}, {%8,%9}, {%0,%1,%2,%3};\n"
                        : "+f"(acc[mm][nn][0]), "+f"(acc[mm][nn][1]),
                          "+f"(acc[mm][nn][2]), "+f"(acc[mm][nn][3])
                        : "r"(af[mm][0]), "r"(af[mm][1]), "r"(af[mm][2]), "r"(af[mm][3]),
                          "r"(b0), "r"(b1));
                }
        }
    };

    int slotC = 0, slotP = 3;
    for (int s = 0; s < KT; s += 2) {
        asm volatile("cp.async.wait_group %0;\n" :: "n"(1));
        __syncthreads();

        if (s + 3 < KT) load_body(slotP, s + 3);
        asm volatile("cp.async.commit_group;\n");
        int slotP2 = slotP + 1; if (slotP2 >= NSLOT) slotP2 -= NSLOT;
        if (s + 4 < KT) load_body(slotP2, s + 4);
        asm volatile("cp.async.commit_group;\n");

        compute_stage(slotC);
        int slotC2 = slotC + 1; if (slotC2 >= NSLOT) slotC2 -= NSLOT;
        compute_stage(slotC2);

        slotC += 2; if (slotC >= NSLOT) slotC -= NSLOT;
        slotP += 2; if (slotP >= NSLOT) slotP -= NSLOT;
    }

    // ---- epilogue ----
    float rsum = rsum0 + rsum1, rsq = rsq0 + rsq1;
    __syncthreads();
    if (tid < 128) { s_m[tid] = rsum; s_r[tid] = rsq; }
    __syncthreads();
    if (tid >= 128) { s_m[tid - 128] += rsum; s_r[tid - 128] += rsq; }
    __syncthreads();
    if (tid < 128) {
        float mu  = s_m[tid] * (1.0f / (float)KDIM);
        float var = s_r[tid] * (1.0f / (float)KDIM) - mu * mu;
        s_m[tid] = mu;
        s_r[tid] = rsqrtf(var + 1e-5f);
        s_c0[tid] = g_colsum[colB0 + tid];
        s_c1[tid] = g_bsum[colB0 + tid];
    }
    __syncthreads();

    int g = lane >> 2, t4 = lane & 3;
    #pragma unroll
    for (int mm = 0; mm < 4; mm++) {
        #pragma unroll
        for (int nn = 0; nn < 4; nn++) {
            #pragma unroll
            for (int rh = 0; rh < 2; rh++) {
                int rl = wm + mm * 16 + g + rh * 8;
                int cl = wn + nn * 8 + 2 * t4;
                float v0 = acc[mm][nn][rh * 2 + 0];
                float v1 = acc[mm][nn][rh * 2 + 1];
                float p0 = s_r[rl] * (v0 - s_m[rl] * s_c0[cl])     + s_c1[cl];
                float p1 = s_r[rl] * (v1 - s_m[rl] * s_c0[cl + 1]) + s_c1[cl + 1];
                __half2 o = __floats2half2_rn(gelu_t(p0), gelu_t(p1));
                *reinterpret_cast<__half2*>(
                    CoutH + (size_t)(rowA0 + rl) * C_DIM + colB0 + cl) = o;
            }
        }
    }
}

// ---------------- K3: FP16 GEMM, small tiles, 3 CTAs/SM (24 warps) ------------
// C[M,768] = A[M,768] @ B[768,768]^T + bias.  BM=64, BN=128, warp tile 32x32.
#define K3BM 64
#define K3BN 128
#define K3LDH 40
#define K3SLOTS 4
#define K3TILE_A (K3BM * K3LDH)              // 2560 halves
#define K3TILE_B (K3BN * K3LDH)              // 5120 halves
#define K3STAGE_B ((K3TILE_A + K3TILE_B) * 2)   // 15360 B
#define K3SMEM (K3SLOTS * K3STAGE_B)            // 61440 B

__global__ __launch_bounds__(256, 3) void gemm_k3(
        const __half* __restrict__ Ag, const __half* __restrict__ Bg,
        const float* __restrict__ bias, float* __restrict__ CoutF) {
    extern __shared__ __half smh[];
    __shared__ float s_c1[K3BN];
    const int KDIM = C_DIM;

    int tid = threadIdx.x;
    int rowA0 = blockIdx.y * K3BM;
    int colB0 = blockIdx.x * K3BN;
    const __half* Abase = Ag + (size_t)rowA0 * KDIM;
    const __half* Bbase = Bg + (size_t)colB0 * KDIM;

    uint32_t smem_u = (uint32_t)__cvta_generic_to_shared(smh);

    // loaders: A 64 rows x 64B (4 thr/row x 16B), B 128 rows x 64B (2 thr/row x 32B)
    int arow = tid >> 2, acol = (tid & 3) * 8;         // halves
    uint32_t aOff = (uint32_t)((arow * K3LDH + acol) * 2);
    int brow = tid >> 1, bcol = (tid & 1) * 16;        // halves
    uint32_t bOff = (uint32_t)((K3TILE_A + brow * K3LDH + bcol) * 2);

    auto load_stage = [&](int slot, int kt) {
        uint32_t base = smem_u + (uint32_t)slot * K3STAGE_B;
        cp16(base + aOff, Abase + (size_t)arow * KDIM + kt * BK + acol);
        const __half* bg = Bbase + (size_t)brow * KDIM + kt * BK + bcol;
        cp16(base + bOff,      bg);
        cp16(base + bOff + 16, bg + 8);
        asm volatile("cp.async.commit_group;\n");
    };

    const int KT = KDIM / BK;        // 24
    #pragma unroll
    for (int p = 0; p < K3SLOTS - 1; p++) load_stage(p, p);

    int wid = tid >> 5, lane = tid & 31;
    int wm = (wid & 1) * 32;         // 2 groups over M=64
    int wn = (wid >> 1) * 32;        // 4 groups over N=128

    uint32_t offA[2];
    #pragma unroll
    for (int mm = 0; mm < 2; mm++) {
        int row = wm + mm * 16 + (lane & 15);
        int kb  = lane >> 4;
        offA[mm] = (uint32_t)((row * K3LDH + kb * 8) * 2);
    }
    uint32_t offB[2];
    #pragma unroll
    for (int nn2 = 0; nn2 < 2; nn2++) {
        int n  = wn + nn2 * 16 + (lane & 7) + ((lane >> 4) ? 8 : 0);
        int kb = (lane >> 3) & 1;
        offB[nn2] = (uint32_t)((K3TILE_A + n * K3LDH + kb * 8) * 2);
    }

    float acc[2][4][4];
    #pragma unroll
    for (int a = 0; a < 2; a++)
        #pragma unroll
        for (int b2 = 0; b2 < 4; b2++)
            #pragma unroll
            for (int c2 = 0; c2 < 4; c2++) acc[a][b2][c2] = 0.f;

    for (int s = 0; s < KT; s++) {
        asm volatile("cp.async.wait_group %0;\n" :: "n"(K3SLOTS - 2));
        __syncthreads();

        int p = s + K3SLOTS - 1;
        if (p < KT) load_stage(p % K3SLOTS, p);

        uint32_t stage = smem_u + (uint32_t)(s % K3SLOTS) * K3STAGE_B;

        #pragma unroll
        for (int kk = 0; kk < BK; kk += 16) {
            uint32_t af[2][4], bf[2][4];
            #pragma unroll
            for (int mm = 0; mm < 2; mm++)
                asm volatile(
                    "ldmatrix.sync.aligned.m8n8.x4.shared.b16 {%0,%1,%2,%3}, [%4];\n"
                    : "=r"(af[mm][0]), "=r"(af[mm][1]), "=r"(af[mm][2]), "=r"(af[mm][3])
                    : "r"(stage + offA[mm] + kk * 2));
            #pragma unroll
            for (int nn2 = 0; nn2 < 2; nn2++)
                asm volatile(
                    "ldmatrix.sync.aligned.m8n8.x4.shared.b16 {%0,%1,%2,%3}, [%4];\n"
                    : "=r"(bf[nn2][0]), "=r"(bf[nn2][1]), "=r"(bf[nn2][2]), "=r"(bf[nn2][3])
                    : "r"(stage + offB[nn2] + kk * 2));

            #pragma unroll
            for (int mm = 0; mm < 2; mm++)
                #pragma unroll
                for (int nn = 0; nn < 4; nn++) {
                    const uint32_t b0 = bf[nn >> 1][(nn & 1) * 2 + 0];
                    const uint32_t b1 = bf[nn >> 1][(nn & 1) * 2 + 1];
                    asm volatile(
                        "mma.sync.aligned.m16n8k16.row.col.f32.f16.f16.f32 "
                        "{%0,%1,%2,%3}, {%4,%5,%6,%7}, {%8,%9}, {%0,%1,%2,%3};\n"
                        : "+f"(acc[mm][nn][0]), "+f"(acc[mm][nn][1]),
                          "+f"(acc[mm][nn][2]), "+f"(acc[mm][nn][3])
                        : "r"(af[mm][0]), "r"(af[mm][1]), "r"(af[mm][2]), "r"(af[mm][3]),
                          "r"(b0), "r"(b1));
                }
        }
    }

    // ---- epilogue ----
    __syncthreads();
    if (tid < K3BN) s_c1[tid] = bias[colB0 + tid];
    __syncthreads();

    int g = lane >> 2, t4 = lane & 3;
    #pragma unroll
    for (int mm = 0; mm < 2; mm++) {
        #pragma unroll
        for (int nn = 0; nn < 4; nn++) {
            #pragma unroll
            for (int rh = 0; rh < 2; rh++) {
                int rl = wm + mm * 16 + g + rh * 8;
                int cl = wn + nn * 8 + 2 * t4;
                float2 o = make_float2(acc[mm][nn][rh * 2 + 0] + s_c1[cl],
                                       acc[mm][nn][rh * 2 + 1] + s_c1[cl + 1]);
                *reinterpret_cast<float2*>(
                    CoutF + (size_t)(rowA0 + rl) * C_DIM + colB0 + cl) = o;
            }
        }
    }
}

// ---------------- launch ----------------
extern "C" void kernel_launch(void* const* d_in, const int* in_sizes, int n_in,
                              void* d_out, int out_size) {
    const float* x     = (const float*)d_in[0];
    const float* ln1w  = (const float*)d_in[1];
    const float* ln1b  = (const float*)d_in[2];
    const float* fc1w  = (const float*)d_in[3];
    const float* ln2w  = (const float*)d_in[4];
    const float* ln2b  = (const float*)d_in[5];
    const float* fc2w  = (const float*)d_in[6];
    const float* projw = (const float*)d_in[7];
    const float* projb = (const float*)d_in[8];
    float* out = (float*)d_out;

    cudaFuncSetAttribute(gemm_k2, cudaFuncAttributeMaxDynamicSharedMemorySize, SMEM_BYTES);
    cudaFuncSetAttribute(gemm_k3, cudaFuncAttributeMaxDynamicSharedMemorySize, K3SMEM);

    prep_all<<<C_DIM, 256>>>(fc2w, ln2w, ln2b, projw);

    stage1<<<dim3(BATCH, 3), 256>>>(x, ln1w, ln1b, fc1w);

    __half* xfuse_p; cudaGetSymbolAddress((void**)&xfuse_p, g_xfuse);
    __half* y_p;     cudaGetSymbolAddress((void**)&y_p,     g_y);
    __half* fc2_p;   cudaGetSymbolAddress((void**)&fc2_p,   g_fc2p);
    __half* proj_p;  cudaGetSymbolAddress((void**)&proj_p,  g_projp);

    gemm_k2<<<dim3(C_DIM / BN, TOKENS / BM), GTHREADS, SMEM_BYTES>>>(
        xfuse_p, fc2_p, y_p);
    gemm_k3<<<dim3(C_DIM / K3BN, TOKENS / K3BM), 256, K3SMEM>>>(
        y_p, proj_p, projb, out);
}